// round 3
// baseline (speedup 1.0000x reference)
#include <cuda_runtime.h>

#define N_G 256
#define D 1024
#define D4 (D / 4)
#define KSPLIT 8
#define KSLICE (D / KSPLIT)   // 128

#define BM 64
#define BN 64
#define BK 16

// Static device scratch (allocation-free rule)
__device__ float g_A[N_G * D];                 // group-mean of im rows (scaled 1/nc)
__device__ float g_B[N_G * D];                 // group-mean of s  rows (scaled 1/ncap)
__device__ float g_diag[N_G];
__device__ float g_Sp[KSPLIT][N_G * N_G];      // split-K partial S

// ---------------------------------------------------------------------------
// K1: segmented row sums, scaled by 1/count. Blocks 0..255 -> im groups,
//     256..511 -> s groups. 256 threads, each owns one float4 column slot.
//     Rows unrolled x4 with independent accumulators for MLP>=4.
// ---------------------------------------------------------------------------
__global__ __launch_bounds__(256)
void k_groupsum(const float* __restrict__ im, const float* __restrict__ s,
                const int* __restrict__ ncl, const int* __restrict__ nca,
                float* __restrict__ out) {
    __shared__ int scnt[N_G];
    __shared__ int soff;

    int b = blockIdx.x;
    bool isB = (b >= N_G);
    int g = isB ? b - N_G : b;
    const int* cnts = isB ? nca : ncl;
    int t = threadIdx.x;

    scnt[t] = cnts[t];                 // coalesced; avoid serial LDG scan
    if (b == 0) {
        g_diag[t] = 0.f;               // zero diag accumulator for K2 epilogue
        if (t == 0) out[0] = 0.f;
    }
    __syncthreads();
    if (t == 0) {
        int o = 0;
        for (int k = 0; k < g; k++) o += scnt[k];   // LDS scan, cheap
        soff = o;
    }
    __syncthreads();

    int off = soff, cnt = scnt[g];
    const float4* src = (const float4*)(isB ? s : im);
    src += (long)off * D4 + t;

    float4 a0 = make_float4(0.f, 0.f, 0.f, 0.f);
    float4 a1 = a0, a2 = a0, a3 = a0;
    int r = 0;
    for (; r + 4 <= cnt; r += 4) {
        float4 v0 = src[(long)(r + 0) * D4];
        float4 v1 = src[(long)(r + 1) * D4];
        float4 v2 = src[(long)(r + 2) * D4];
        float4 v3 = src[(long)(r + 3) * D4];
        a0.x += v0.x; a0.y += v0.y; a0.z += v0.z; a0.w += v0.w;
        a1.x += v1.x; a1.y += v1.y; a1.z += v1.z; a1.w += v1.w;
        a2.x += v2.x; a2.y += v2.y; a2.z += v2.z; a2.w += v2.w;
        a3.x += v3.x; a3.y += v3.y; a3.z += v3.z; a3.w += v3.w;
    }
    for (; r < cnt; r++) {
        float4 v = src[(long)r * D4];
        a0.x += v.x; a0.y += v.y; a0.z += v.z; a0.w += v.w;
    }
    float4 acc;
    acc.x = (a0.x + a1.x) + (a2.x + a3.x);
    acc.y = (a0.y + a1.y) + (a2.y + a3.y);
    acc.z = (a0.z + a1.z) + (a2.z + a3.z);
    acc.w = (a0.w + a1.w) + (a2.w + a3.w);

    float inv = 1.f / (float)cnt;
    acc.x *= inv; acc.y *= inv; acc.z *= inv; acc.w *= inv;

    float4* dst = (float4*)(isB ? g_B : g_A);
    dst[g * D4 + t] = acc;
}

// ---------------------------------------------------------------------------
// K2: split-K GEMM  S_partial[kz] = A[:, kz-slice] @ B[:, kz-slice]^T
//     grid (4,4,8), 256 threads, 64x64 tile, 4x4 micro per thread.
//     Diagonal CTAs (ib==jb) also accumulate diag via atomicAdd.
// ---------------------------------------------------------------------------
__global__ __launch_bounds__(256)
void k_gemm() {
    __shared__ float As[BK][BM];
    __shared__ float Bs[BK][BN];

    int ib = blockIdx.x, jb = blockIdx.y, kz = blockIdx.z;
    int tid = threadIdx.x;
    int tx = tid & 15;          // output col group
    int ty = tid >> 4;          // output row group
    int lm = tid & 63;          // load: row within tile
    int lk = (tid >> 6) << 2;   // load: k offset {0,4,8,12}

    const float4* Ag = (const float4*)g_A;
    const float4* Bg = (const float4*)g_B;

    float acc[4][4] = {};

    int k0base = kz * KSLICE;
    for (int kc = 0; kc < KSLICE; kc += BK) {
        int kq = (k0base + kc + lk) >> 2;
        float4 av = Ag[(ib * BM + lm) * D4 + kq];
        float4 bv = Bg[(jb * BN + lm) * D4 + kq];
        __syncthreads();
        As[lk + 0][lm] = av.x; As[lk + 1][lm] = av.y;
        As[lk + 2][lm] = av.z; As[lk + 3][lm] = av.w;
        Bs[lk + 0][lm] = bv.x; Bs[lk + 1][lm] = bv.y;
        Bs[lk + 2][lm] = bv.z; Bs[lk + 3][lm] = bv.w;
        __syncthreads();

#pragma unroll
        for (int kk = 0; kk < BK; kk++) {
            float4 a4 = *(const float4*)&As[kk][ty << 2];
            float4 b4 = *(const float4*)&Bs[kk][tx << 2];
            acc[0][0] += a4.x * b4.x; acc[0][1] += a4.x * b4.y;
            acc[0][2] += a4.x * b4.z; acc[0][3] += a4.x * b4.w;
            acc[1][0] += a4.y * b4.x; acc[1][1] += a4.y * b4.y;
            acc[1][2] += a4.y * b4.z; acc[1][3] += a4.y * b4.w;
            acc[2][0] += a4.z * b4.x; acc[2][1] += a4.z * b4.y;
            acc[2][2] += a4.z * b4.z; acc[2][3] += a4.z * b4.w;
            acc[3][0] += a4.w * b4.x; acc[3][1] += a4.w * b4.y;
            acc[3][2] += a4.w * b4.z; acc[3][3] += a4.w * b4.w;
        }
    }

    float* Sp = g_Sp[kz];
#pragma unroll
    for (int r = 0; r < 4; r++) {
        int i = ib * BM + (ty << 2) + r;
        float4 v = make_float4(acc[r][0], acc[r][1], acc[r][2], acc[r][3]);
        *(float4*)&Sp[i * N_G + jb * BN + (tx << 2)] = v;
    }

    // Diagonal contribution: tile on the global diagonal, threads with tx==ty
    // own the local-diagonal 4x4 micro-tiles.
    if (ib == jb && tx == ty) {
#pragma unroll
        for (int r = 0; r < 4; r++)
            atomicAdd(&g_diag[ib * BM + (ty << 2) + r], acc[r][r]);
    }
}

// ---------------------------------------------------------------------------
// K3: loss = sum_{i!=j} max(S_ij - diag_i, 0) + max(S_ij - diag_j, 0)
//     grid 256 (one block per row i), 256 threads (one per col j).
//     8 independent partial loads per thread -> full MLP.
// ---------------------------------------------------------------------------
__global__ __launch_bounds__(256)
void k_loss(float* __restrict__ out) {
    int i = blockIdx.x;
    int j = threadIdx.x;
    int idx = i * N_G + j;

    float sv = 0.f;
#pragma unroll
    for (int z = 0; z < KSPLIT; z++) sv += g_Sp[z][idx];

    float di = g_diag[i];   // broadcast
    float dj = g_diag[j];   // coalesced

    float sum = 0.f;
    if (i != j)
        sum = fmaxf(sv - di, 0.f) + fmaxf(sv - dj, 0.f);

    // warp reduce then cross-warp via shared
#pragma unroll
    for (int st = 16; st > 0; st >>= 1)
        sum += __shfl_xor_sync(0xFFFFFFFF, sum, st);

    __shared__ float red[8];
    if ((j & 31) == 0) red[j >> 5] = sum;
    __syncthreads();
    if (j < 8) {
        float v = red[j];
#pragma unroll
        for (int st = 4; st > 0; st >>= 1)
            v += __shfl_xor_sync(0xFF, v, st);
        if (j == 0) atomicAdd(out, v);
    }
}

// ---------------------------------------------------------------------------
extern "C" void kernel_launch(void* const* d_in, const int* in_sizes, int n_in,
                              void* d_out, int out_size) {
    const float* im  = (const float*)d_in[0];
    const float* s   = (const float*)d_in[1];
    const int*   ncl = (const int*)d_in[2];
    const int*   nca = (const int*)d_in[3];
    float* out = (float*)d_out;

    k_groupsum<<<2 * N_G, 256>>>(im, s, ncl, nca, out);
    dim3 g2(N_G / BM, N_G / BN, KSPLIT);
    k_gemm<<<g2, 256>>>();
    k_loss<<<N_G, 256>>>(out);
}

// round 4
// speedup vs baseline: 1.1905x; 1.1905x over previous
#include <cuda_runtime.h>

#define N_G 256
#define D 1024
#define D4 (D / 4)
#define KSPLIT 16
#define KSLICE (D / KSPLIT)   // 64

#define BM 64
#define BN 64
#define BK 16

#define ROWS_A 4088
#define ROWS_B 4091
#define CHUNK 8
#define NCH_A ((ROWS_A + CHUNK - 1) / CHUNK)   // 511
#define NCH_B ((ROWS_B + CHUNK - 1) / CHUNK)   // 512

// Static device scratch (allocation-free rule)
__device__ float g_Asum[N_G * D];              // UNSCALED group sums of im
__device__ float g_Bsum[N_G * D];              // UNSCALED group sums of s
__device__ float g_invA[N_G], g_invB[N_G];     // 1/num_clips, 1/num_caps
__device__ int   g_offA[N_G + 1], g_offB[N_G + 1];
__device__ float g_diag[N_G];                  // unscaled diagonal of S
__device__ float g_Sp[KSPLIT][N_G * N_G];      // split-K partial S (unscaled)

// ---------------------------------------------------------------------------
// K0: zero accumulators; block 0 computes prefix offsets + reciprocals.
//     grid 256 x 256 threads.
// ---------------------------------------------------------------------------
__global__ __launch_bounds__(256)
void k_prep(const int* __restrict__ ncl, const int* __restrict__ nca,
            float* __restrict__ out) {
    int idx = blockIdx.x * 256 + threadIdx.x;   // [0, 65536)
    ((float4*)g_Asum)[idx] = make_float4(0.f, 0.f, 0.f, 0.f);
    ((float4*)g_Bsum)[idx] = make_float4(0.f, 0.f, 0.f, 0.f);

    if (blockIdx.x == 0) {
        int t = threadIdx.x;
        __shared__ int sa[N_G], sb[N_G];
        int ca = ncl[t], cb = nca[t];
        sa[t] = ca; sb[t] = cb;
        g_invA[t] = 1.f / (float)ca;
        g_invB[t] = 1.f / (float)cb;
        g_diag[t] = 0.f;
        if (t == 0) { out[0] = 0.f; g_offA[0] = 0; g_offB[0] = 0; }
        __syncthreads();
        // Hillis-Steele inclusive scan
        for (int d = 1; d < N_G; d <<= 1) {
            int va = (t >= d) ? sa[t - d] : 0;
            int vb = (t >= d) ? sb[t - d] : 0;
            __syncthreads();
            sa[t] += va; sb[t] += vb;
            __syncthreads();
        }
        g_offA[t + 1] = sa[t];
        g_offB[t + 1] = sb[t];
    }
}

// ---------------------------------------------------------------------------
// K1: balanced segmented sums. Each CTA owns CHUNK=8 consecutive rows
//     (blocks [0,511) -> im, [511, 1023) -> s). 256 threads = one float4
//     column each. All 8 loads front-batched (MLP=8), then a segment walk
//     flushes into g_{A,B}sum via atomicAdd (few flushes: rows/group >= 8).
// ---------------------------------------------------------------------------
__global__ __launch_bounds__(256)
void k_seg(const float* __restrict__ im, const float* __restrict__ s) {
    int b = blockIdx.x;
    bool isB = (b >= NCH_A);
    int cb = isB ? b - NCH_A : b;
    int Rtot = isB ? ROWS_B : ROWS_A;
    int r0 = cb * CHUNK;
    int t = threadIdx.x;

    __shared__ int soff[N_G + 1];
    const int* offsrc = isB ? g_offB : g_offA;
    soff[t] = offsrc[t];
    if (t == 0) soff[N_G] = offsrc[N_G];
    __syncthreads();

    int nrows = Rtot - r0; if (nrows > CHUNK) nrows = CHUNK;

    const float4* src = (const float4*)(isB ? s : im) + (size_t)r0 * D4 + t;
    float4 v[CHUNK];
#pragma unroll
    for (int u = 0; u < CHUNK; u++)
        v[u] = (u < nrows) ? src[(size_t)u * D4] : make_float4(0.f, 0.f, 0.f, 0.f);

    // group of r0: binary search over boundaries (uniform across CTA)
    int lo = 0, hi = N_G - 1;
    while (lo < hi) {
        int mid = (lo + hi + 1) >> 1;
        if (soff[mid] <= r0) lo = mid; else hi = mid - 1;
    }
    int gidx = lo;
    int gend = soff[gidx + 1];
    float* gs = isB ? g_Bsum : g_Asum;

    float4 acc = make_float4(0.f, 0.f, 0.f, 0.f);
#pragma unroll
    for (int u = 0; u < CHUNK; u++) {
        if (u < nrows && r0 + u == gend) {
            float* p = gs + (size_t)gidx * D + t * 4;
            atomicAdd(p + 0, acc.x); atomicAdd(p + 1, acc.y);
            atomicAdd(p + 2, acc.z); atomicAdd(p + 3, acc.w);
            acc = make_float4(0.f, 0.f, 0.f, 0.f);
            gidx++; gend = soff[gidx + 1];
        }
        acc.x += v[u].x; acc.y += v[u].y; acc.z += v[u].z; acc.w += v[u].w;
    }
    float* p = gs + (size_t)gidx * D + t * 4;
    atomicAdd(p + 0, acc.x); atomicAdd(p + 1, acc.y);
    atomicAdd(p + 2, acc.z); atomicAdd(p + 3, acc.w);
}

// ---------------------------------------------------------------------------
// K2: split-K GEMM  S_partial[kz] = Asum[:, slice] @ Bsum[:, slice]^T
//     grid (4,4,16), 256 threads, 64x64 tile, 4x4 micro per thread.
//     Diagonal CTAs also accumulate the (unscaled) diagonal.
// ---------------------------------------------------------------------------
__global__ __launch_bounds__(256)
void k_gemm() {
    __shared__ float As[BK][BM];
    __shared__ float Bs[BK][BN];

    int ib = blockIdx.x, jb = blockIdx.y, kz = blockIdx.z;
    int tid = threadIdx.x;
    int tx = tid & 15;
    int ty = tid >> 4;
    int lm = tid & 63;
    int lk = (tid >> 6) << 2;

    const float4* Ag = (const float4*)g_Asum;
    const float4* Bg = (const float4*)g_Bsum;

    float acc[4][4] = {};

    int k0base = kz * KSLICE;
    for (int kc = 0; kc < KSLICE; kc += BK) {
        int kq = (k0base + kc + lk) >> 2;
        float4 av = Ag[(ib * BM + lm) * D4 + kq];
        float4 bv = Bg[(jb * BN + lm) * D4 + kq];
        __syncthreads();
        As[lk + 0][lm] = av.x; As[lk + 1][lm] = av.y;
        As[lk + 2][lm] = av.z; As[lk + 3][lm] = av.w;
        Bs[lk + 0][lm] = bv.x; Bs[lk + 1][lm] = bv.y;
        Bs[lk + 2][lm] = bv.z; Bs[lk + 3][lm] = bv.w;
        __syncthreads();

#pragma unroll
        for (int kk = 0; kk < BK; kk++) {
            float4 a4 = *(const float4*)&As[kk][ty << 2];
            float4 b4 = *(const float4*)&Bs[kk][tx << 2];
            acc[0][0] += a4.x * b4.x; acc[0][1] += a4.x * b4.y;
            acc[0][2] += a4.x * b4.z; acc[0][3] += a4.x * b4.w;
            acc[1][0] += a4.y * b4.x; acc[1][1] += a4.y * b4.y;
            acc[1][2] += a4.y * b4.z; acc[1][3] += a4.y * b4.w;
            acc[2][0] += a4.z * b4.x; acc[2][1] += a4.z * b4.y;
            acc[2][2] += a4.z * b4.z; acc[2][3] += a4.z * b4.w;
            acc[3][0] += a4.w * b4.x; acc[3][1] += a4.w * b4.y;
            acc[3][2] += a4.w * b4.z; acc[3][3] += a4.w * b4.w;
        }
    }

    float* Sp = g_Sp[kz];
#pragma unroll
    for (int r = 0; r < 4; r++) {
        int i = ib * BM + (ty << 2) + r;
        float4 v = make_float4(acc[r][0], acc[r][1], acc[r][2], acc[r][3]);
        *(float4*)&Sp[i * N_G + jb * BN + (tx << 2)] = v;
    }

    if (ib == jb && tx == ty) {
#pragma unroll
        for (int r = 0; r < 4; r++)
            atomicAdd(&g_diag[ib * BM + (ty << 2) + r], acc[r][r]);
    }
}

// ---------------------------------------------------------------------------
// K3: loss with count-scaling folded in.
//     S_ij = sv * invA[i] * invB[j];  diag_i = g_diag[i] * invA[i] * invB[i]
//     grid 256 (row i) x 256 threads (col j). 16 independent partial loads.
// ---------------------------------------------------------------------------
__global__ __launch_bounds__(256)
void k_loss(float* __restrict__ out) {
    int i = blockIdx.x;
    int j = threadIdx.x;
    int idx = i * N_G + j;

    float sv = 0.f;
#pragma unroll
    for (int z = 0; z < KSPLIT; z++) sv += g_Sp[z][idx];

    float ai = g_invA[i];          // broadcast
    float bi = g_invB[i];          // broadcast
    float aj = g_invA[j];          // coalesced
    float bj = g_invB[j];          // coalesced
    float di = g_diag[i] * ai * bi;
    float dj = g_diag[j] * aj * bj;
    float S  = sv * ai * bj;

    float sum = 0.f;
    if (i != j)
        sum = fmaxf(S - di, 0.f) + fmaxf(S - dj, 0.f);

#pragma unroll
    for (int st = 16; st > 0; st >>= 1)
        sum += __shfl_xor_sync(0xFFFFFFFF, sum, st);

    __shared__ float red[8];
    if ((j & 31) == 0) red[j >> 5] = sum;
    __syncthreads();
    if (j < 8) {
        float v = red[j];
#pragma unroll
        for (int st = 4; st > 0; st >>= 1)
            v += __shfl_xor_sync(0xFF, v, st);
        if (j == 0) atomicAdd(out, v);
    }
}

// ---------------------------------------------------------------------------
extern "C" void kernel_launch(void* const* d_in, const int* in_sizes, int n_in,
                              void* d_out, int out_size) {
    const float* im  = (const float*)d_in[0];
    const float* s   = (const float*)d_in[1];
    const int*   ncl = (const int*)d_in[2];
    const int*   nca = (const int*)d_in[3];
    float* out = (float*)d_out;

    k_prep<<<256, 256>>>(ncl, nca, out);
    k_seg<<<NCH_A + NCH_B, 256>>>(im, s);
    dim3 g2(N_G / BM, N_G / BN, KSPLIT);
    k_gemm<<<g2, 256>>>();
    k_loss<<<N_G, 256>>>(out);
}